// round 3
// baseline (speedup 1.0000x reference)
#include <cuda_runtime.h>
#include <math.h>

namespace {

constexpr int DKP = 28;              // padded factor dim (25 -> 28, 16B aligned)
constexpr int NDIM = 2 * DKP;        // 56 floats = 224B per node
constexpr int TOTAL_NODES = 180000;  // 60000 + 30000 + 6*15000
constexpr int TOTAL_ROWS  = 270000;  // 60000 + 7*30000
constexpr int TOTAL_COLS  = 180000;  // 30000 + 60000 + 6*15000
constexpr int TOTAL_EDGES = 3800000; // 2*1e6 + 6*3e5
constexpr int OUT_ROWS = 90000;
constexpr int SCAN_NBLK = (TOTAL_ROWS + 1023) / 1024; // 264

__constant__ int c_EOFF[9] = {0,1000000,2000000,2300000,2600000,2900000,3200000,3500000,3800000};
__constant__ int c_ROFF[9] = {0,60000,90000,120000,150000,180000,210000,240000,270000};
__constant__ int c_COFF[9] = {0,30000,90000,105000,120000,135000,150000,165000,180000};
__constant__ int c_TOFF[9] = {0,60000,90000,105000,120000,135000,150000,165000,180000};
__constant__ int c_SRC[8]  = {0,1,1,1,1,1,1,1};
__constant__ int c_DST[8]  = {1,0,2,3,4,5,6,7};

__device__ float g_emb[(size_t)TOTAL_NODES * NDIM + 16]; // projected embeddings, pads zero
__device__ float g_z  [(size_t)TOTAL_ROWS  * NDIM];      // per-relation messages
__device__ float g_p  [TOTAL_ROWS * 2];
__device__ float g_q  [TOTAL_COLS * 2];
__device__ float g_r  [TOTAL_ROWS * 2];
// zeroed by ONE memset each launch: [rowcnt | fill | scanflag]
__device__ int   g_zero[TOTAL_ROWS * 2 + SCAN_NBLK];
__device__ int   g_rowptr[TOTAL_ROWS + 1];
__device__ int   g_blocksum[SCAN_NBLK];
__device__ int   g_colidx[TOTAL_EDGES];

struct Ptrs {
    const int*   edge[8];
    const float* embin[8];
    const float* Wtk;
    const float* at;
    const float* W;
    const float* q_rela;
};

__device__ __forceinline__ int find_seg8(const int* off, int x) {
    int e = 0;
    #pragma unroll
    for (int i = 1; i < 8; i++) e += (x >= off[i]);
    return e;
}

__device__ __forceinline__ float fast_tanh(float x) {
    float y;
    asm("tanh.approx.f32 %0, %1;" : "=f"(y) : "f"(x));
    return y;
}

__device__ __forceinline__ float dot25(const float* v, const float* a) {
    float s = 0.f;
    #pragma unroll
    for (int d = 0; d < 25; d++) s += v[d] * __ldg(&a[d]);
    return s;
}

// write p (per src relation) and q (per dst relation) for node (type t, local n, factor k)
__device__ __forceinline__ void write_pq(int t, int n, int k, const float* vec, const float* at) {
    if (t == 0) {
        g_p[(c_ROFF[0] + n) * 2 + k] = dot25(vec, at + (0 * 2 + k) * 50);
        g_q[(c_COFF[1] + n) * 2 + k] = dot25(vec, at + (1 * 2 + k) * 50 + 25);
    } else if (t == 1) {
        #pragma unroll
        for (int e = 1; e < 8; e++)
            g_p[(c_ROFF[e] + n) * 2 + k] = dot25(vec, at + (e * 2 + k) * 50);
        g_q[(c_COFF[0] + n) * 2 + k] = dot25(vec, at + (0 * 2 + k) * 50 + 25);
    } else {
        g_q[(c_COFF[t] + n) * 2 + k] = dot25(vec, at + (t * 2 + k) * 50 + 25);
    }
}

// ---------------- initial projection + fused p/q ----------------------------------
__global__ void __launch_bounds__(128) k_init(Ptrs P) {
    __shared__ float Wsh[2][2][50 * 25];   // [which-type][k][d*25+f]
    int base_slot = blockIdx.x * 128;
    int node0 = base_slot >> 1;
    int nlast = (base_slot + 127) >> 1;
    if (nlast > TOTAL_NODES - 1) nlast = TOTAL_NODES - 1;
    int t0 = find_seg8(c_TOFF, node0);
    int t1 = find_seg8(c_TOFF, nlast);
    for (int i = threadIdx.x; i < 2 * 50 * 25; i += 128) {
        Wsh[0][0][i] = P.Wtk[(size_t)t0 * 2 * 50 * 25 + i];
        Wsh[1][0][i] = P.Wtk[(size_t)t1 * 2 * 50 * 25 + i];
    }
    __syncthreads();
    int slot = base_slot + threadIdx.x;
    if (slot >= TOTAL_NODES * 2) return;
    int node = slot >> 1, k = slot & 1;
    int t = find_seg8(c_TOFF, node);
    int sel = (t == t0) ? 0 : 1;
    const float* x = P.embin[t] + (size_t)(node - c_TOFF[t]) * 50;
    const float* w = &Wsh[sel][k][0];
    float out[25];
    #pragma unroll
    for (int f = 0; f < 25; f++) out[f] = 0.f;
    for (int d = 0; d < 50; d++) {
        float xd = __ldg(&x[d]);
        #pragma unroll
        for (int f = 0; f < 25; f++) out[f] += xd * w[d * 25 + f];
    }
    float nrm = 0.f;
    #pragma unroll
    for (int f = 0; f < 25; f++) {
        float s = out[f];
        s = (s >= 0.f) ? s : 0.2f * s;
        out[f] = s;
        nrm += s * s;
    }
    float inv = 1.f / fmaxf(sqrtf(nrm), 1e-12f);
    #pragma unroll
    for (int f = 0; f < 25; f++) out[f] *= inv;
    float* dst = g_emb + (size_t)node * NDIM + k * DKP;
    #pragma unroll
    for (int f = 0; f < 25; f++) dst[f] = out[f];
    dst[25] = 0.f; dst[26] = 0.f; dst[27] = 0.f;
    write_pq(t, node - c_TOFF[t], k, out, P.at);
}

// ---------------- CSR build (edges constant across iterations) --------------------
__global__ void k_hist(Ptrs P) {
    int j = blockIdx.x * blockDim.x + threadIdx.x;
    if (j >= TOTAL_EDGES) return;
    int e = find_seg8(c_EOFF, j);
    int le = j - c_EOFF[e];
    int u = P.edge[e][le];
    atomicAdd(&g_zero[c_ROFF[e] + u], 1);   // rowcnt
}

// single-kernel chained scan: all 264 blocks co-resident (1024 thr, 2 blk/SM)
__global__ void __launch_bounds__(1024, 2) k_scan() {
    __shared__ int sh[1024];
    __shared__ int sh_prefix;
    int bid = blockIdx.x, tid = threadIdx.x;
    int i = bid * 1024 + tid;
    int v = (i < TOTAL_ROWS) ? g_zero[i] : 0;   // rowcnt
    sh[tid] = v;
    __syncthreads();
    #pragma unroll
    for (int off = 1; off < 1024; off <<= 1) {
        int t = (tid >= off) ? sh[tid - off] : 0;
        __syncthreads();
        sh[tid] += t;
        __syncthreads();
    }
    int incl = sh[tid];
    int total = sh[1023];
    if (tid == 0) {
        int prefix = 0;
        if (bid > 0) {
            volatile int* flag = (volatile int*)&g_zero[2 * TOTAL_ROWS];
            while (flag[bid - 1] == 0) {}
            prefix = *((volatile int*)&g_blocksum[bid - 1]);
        }
        *((volatile int*)&g_blocksum[bid]) = prefix + total;
        __threadfence();
        *((volatile int*)&g_zero[2 * TOTAL_ROWS + bid]) = 1;
        sh_prefix = prefix;
    }
    __syncthreads();
    int prefix = sh_prefix;
    if (i < TOTAL_ROWS) g_rowptr[i] = prefix + incl - v;
    if (bid == SCAN_NBLK - 1 && tid == 1023) g_rowptr[TOTAL_ROWS] = prefix + total;
}

__global__ void k_fill(Ptrs P) {
    int j = blockIdx.x * blockDim.x + threadIdx.x;
    if (j >= TOTAL_EDGES) return;
    int e = find_seg8(c_EOFF, j);
    int le = j - c_EOFF[e];
    int E = c_EOFF[e + 1] - c_EOFF[e];
    const int* ed = P.edge[e];
    int u = ed[le], c = ed[E + le];
    int row = c_ROFF[e] + u;
    int pos = g_rowptr[row] + atomicAdd(&g_zero[TOTAL_ROWS + row], 1);  // fill
    g_colidx[pos] = c;
}

// ---------------- fused score + softmax + aggregate, single pass (warp/row) -------
// No max-subtraction (scores bounded ~[0,1.6]): w = exp(v) directly, one final
// warp-sum. Broadcast loop 8x-unrolled, dual accumulators, float2 lanes.
__global__ void __launch_bounds__(256) k_row() {
    int row  = (blockIdx.x * 256 + threadIdx.x) >> 5;
    int lane = threadIdx.x & 31;
    if (row >= TOTAL_ROWS) return;
    int e = find_seg8(c_ROFF, row);
    int base = g_rowptr[row];
    int deg  = g_rowptr[row + 1] - base;
    float* zr = g_z + (size_t)row * NDIM;
    if (deg == 0) {
        if (lane < 28) ((float2*)zr)[lane] = make_float2(0.f, 0.f);
        return;
    }
    int coff  = c_COFF[e];
    int nbase = c_TOFF[c_DST[e]];
    float2 pv = ((const float2*)g_p)[row];
    int dlane = (lane < 28) ? lane : 27;   // lanes 28-31 duplicate lane 27

    float s = 0.f;
    float2 accA = make_float2(0.f, 0.f), accB = make_float2(0.f, 0.f);

    for (int i0 = 0; i0 < deg; i0 += 32) {
        int i = i0 + lane;
        int c = 0; float w = 0.f;
        if (i < deg) {
            c = __ldg(&g_colidx[base + i]);
            float2 qv = __ldg(&((const float2*)g_q)[coff + c]);
            float v = 0.5f * (fmaxf(pv.x + qv.x, 0.f) + fmaxf(pv.y + qv.y, 0.f));
            w = __expf(v);
            s += w;
        }
        int nn = deg - i0; if (nn > 32) nn = 32;
        int nn8 = (nn + 7) & ~7;           // inactive lanes have w=0, c=0 -> harmless
        for (int jj = 0; jj < nn8; jj += 8) {
            float aw[8]; int cc[8];
            #pragma unroll
            for (int u = 0; u < 8; u++) {
                aw[u] = __shfl_sync(0xffffffffu, w, jj + u);
                cc[u] = __shfl_sync(0xffffffffu, c, jj + u);
            }
            float2 f[8];
            #pragma unroll
            for (int u = 0; u < 8; u++)
                f[u] = __ldg(&((const float2*)(g_emb + (size_t)(nbase + cc[u]) * NDIM))[dlane]);
            #pragma unroll
            for (int u = 0; u < 8; u += 2) {
                accA.x += aw[u] * f[u].x;     accA.y += aw[u] * f[u].y;
                accB.x += aw[u+1] * f[u+1].x; accB.y += aw[u+1] * f[u+1].y;
            }
        }
    }
    #pragma unroll
    for (int off = 16; off; off >>= 1)
        s += __shfl_xor_sync(0xffffffffu, s, off);
    float invS = 1.f / s;
    if (lane < 28)
        ((float2*)zr)[lane] = make_float2((accA.x + accB.x) * invS,
                                          (accA.y + accB.y) * invS);
}

// ---------------- z' = lrelu(z) @ W ; r = softmax_k( tanh(z') . q_rela ) ----------
__global__ void __launch_bounds__(128) k_transform(Ptrs P) {
    __shared__ float Ws[625];
    for (int i = threadIdx.x; i < 625; i += 128) Ws[i] = P.W[i];
    __syncthreads();
    int row = blockIdx.x * 128 + threadIdx.x;
    if (row >= TOTAL_ROWS) return;
    int e = find_seg8(c_ROFF, row);
    const float* qr = P.q_rela + e * 25;
    float* zr = g_z + (size_t)row * NDIM;
    float s01[2];
    #pragma unroll
    for (int k = 0; k < 2; k++) {
        float lr[25];
        #pragma unroll
        for (int d = 0; d < 25; d++) {
            float v = zr[k * DKP + d];
            lr[d] = (v >= 0.f) ? v : 0.2f * v;
        }
        float sk = 0.f;
        for (int f = 0; f < 25; f++) {
            float sm = 0.f;
            #pragma unroll
            for (int d = 0; d < 25; d++) sm += lr[d] * Ws[d * 25 + f];
            zr[k * DKP + f] = sm;
            sk += fast_tanh(sm) * __ldg(&qr[f]);
        }
        s01[k] = sk;
    }
    float mm = fmaxf(s01[0], s01[1]);
    float e0 = __expf(s01[0] - mm), e1 = __expf(s01[1] - mm);
    float inv = 1.f / (e0 + e1);
    g_r[row * 2 + 0] = e0 * inv;
    g_r[row * 2 + 1] = e1 * inv;
}

// ---------------- ego aggregation + l2 normalize + fused p/q refresh --------------
__global__ void __launch_bounds__(256) k_agg(Ptrs P) {
    int slot = blockIdx.x * 256 + threadIdx.x;
    if (slot >= OUT_ROWS * 2) return;
    int node = slot >> 1, k = slot & 1;
    float acc[25];
    float* er = g_emb + (size_t)node * NDIM + k * DKP;
    #pragma unroll
    for (int d = 0; d < 25; d++) acc[d] = er[d];
    if (node < 60000) {                 // type 0: relation 0 only
        float r = g_r[node * 2 + k];
        const float* zz = g_z + (size_t)node * NDIM + k * DKP;
        #pragma unroll
        for (int d = 0; d < 25; d++) acc[d] += r * zz[d];
    } else {                            // type 1: relations 1..7
        int n = node - 60000;
        #pragma unroll
        for (int e = 1; e < 8; e++) {
            int row = c_ROFF[e] + n;
            float r = g_r[row * 2 + k];
            const float* zz = g_z + (size_t)row * NDIM + k * DKP;
            #pragma unroll
            for (int d = 0; d < 25; d++) acc[d] += r * zz[d];
        }
    }
    float nrm = 0.f;
    #pragma unroll
    for (int d = 0; d < 25; d++) nrm += acc[d] * acc[d];
    float inv = 1.f / fmaxf(sqrtf(nrm), 1e-12f);
    #pragma unroll
    for (int d = 0; d < 25; d++) acc[d] *= inv;
    #pragma unroll
    for (int d = 0; d < 25; d++) er[d] = acc[d];
    int t = (node < 60000) ? 0 : 1;
    write_pq(t, (t == 0) ? node : node - 60000, k, acc, P.at);
}

// ---------------- output: [n, k*25+d] for user then item --------------------------
__global__ void k_out(float* __restrict__ out) {
    int idx = blockIdx.x * blockDim.x + threadIdx.x;
    if (idx >= OUT_ROWS * 50) return;
    int r = idx / 50, c = idx - r * 50;
    int k = c / 25, d = c - k * 25;
    out[idx] = g_emb[(size_t)r * NDIM + k * DKP + d];
}

} // anonymous namespace

extern "C" void kernel_launch(void* const* d_in, const int* in_sizes, int n_in,
                              void* d_out, int out_size) {
    Ptrs P;
    for (int i = 0; i < 8; i++) P.edge[i]  = (const int*)d_in[i];
    for (int i = 0; i < 8; i++) P.embin[i] = (const float*)d_in[8 + i];
    P.Wtk    = (const float*)d_in[16];
    P.at     = (const float*)d_in[17];
    P.W      = (const float*)d_in[18];
    P.q_rela = (const float*)d_in[19];

    void* p_zero = nullptr;
    cudaGetSymbolAddress(&p_zero, g_zero);

    // launch indices 0..4, so k_row (first iter) is launch #5 -> ncu -s 5 lands on it
    k_init<<<(TOTAL_NODES * 2 + 127) / 128, 128>>>(P);                    // 0
    cudaMemsetAsync(p_zero, 0, sizeof(int) * (2 * TOTAL_ROWS + SCAN_NBLK), 0); // 1
    k_hist<<<(TOTAL_EDGES + 255) / 256, 256>>>(P);                        // 2
    k_scan<<<SCAN_NBLK, 1024>>>();                                        // 3
    k_fill<<<(TOTAL_EDGES + 255) / 256, 256>>>(P);                        // 4

    for (int it = 0; it < 4; it++) {
        k_row<<<(TOTAL_ROWS * 32 + 255) / 256, 256>>>();                  // 5 on it=0
        k_transform<<<(TOTAL_ROWS + 127) / 128, 128>>>(P);
        k_agg<<<(OUT_ROWS * 2 + 255) / 256, 256>>>(P);
    }
    k_out<<<(OUT_ROWS * 50 + 255) / 256, 256>>>((float*)d_out);
}

// round 4
// speedup vs baseline: 1.2799x; 1.2799x over previous
#include <cuda_runtime.h>
#include <math.h>

namespace {

constexpr int DKP = 28;              // padded factor dim (25 -> 28, 16B aligned)
constexpr int NDIM = 2 * DKP;        // 56 floats = 224B per node
constexpr int TOTAL_NODES = 180000;  // 60000 + 30000 + 6*15000
constexpr int TOTAL_ROWS  = 270000;  // 60000 + 7*30000
constexpr int TOTAL_COLS  = 180000;  // 30000 + 60000 + 6*15000
constexpr int TOTAL_EDGES = 3800000; // 2*1e6 + 6*3e5
constexpr int OUT_ROWS = 90000;
constexpr int SCAN_ELEMS = 8192;     // per block (1024 thr x 8)
constexpr int SCAN_NBLK = (TOTAL_ROWS + SCAN_ELEMS - 1) / SCAN_ELEMS; // 33

__constant__ int c_EOFF[9] = {0,1000000,2000000,2300000,2600000,2900000,3200000,3500000,3800000};
__constant__ int c_ROFF[9] = {0,60000,90000,120000,150000,180000,210000,240000,270000};
__constant__ int c_COFF[9] = {0,30000,90000,105000,120000,135000,150000,165000,180000};
__constant__ int c_TOFF[9] = {0,60000,90000,105000,120000,135000,150000,165000,180000};
__constant__ int c_SRC[8]  = {0,1,1,1,1,1,1,1};
__constant__ int c_DST[8]  = {1,0,2,3,4,5,6,7};

__device__ float g_emb[(size_t)TOTAL_NODES * NDIM + 16]; // projected embeddings, pads zero
__device__ float g_z  [(size_t)TOTAL_ROWS  * NDIM];      // transformed messages z' = lrelu(z)@W
__device__ float g_p  [TOTAL_ROWS * 2];
__device__ float g_q  [TOTAL_COLS * 2];
__device__ float g_r  [TOTAL_ROWS * 2];
// zeroed by k_zero: [rowcnt | fill | scanflags]
__device__ int   g_zero[TOTAL_ROWS * 2 + SCAN_NBLK];
__device__ int   g_rowptr[TOTAL_ROWS + 1];
__device__ int   g_blocksum[SCAN_NBLK];
__device__ int   g_colidx[TOTAL_EDGES];

struct Ptrs {
    const int*   edge[8];
    const float* embin[8];
    const float* Wtk;
    const float* at;
    const float* W;
    const float* q_rela;
};

__device__ __forceinline__ int find_seg8(const int* off, int x) {
    int e = 0;
    #pragma unroll
    for (int i = 1; i < 8; i++) e += (x >= off[i]);
    return e;
}

__device__ __forceinline__ float fast_tanh(float x) {
    float y;
    asm("tanh.approx.f32 %0, %1;" : "=f"(y) : "f"(x));
    return y;
}

__device__ __forceinline__ float dot25(const float* v, const float* a) {
    float s = 0.f;
    #pragma unroll
    for (int d = 0; d < 25; d++) s += v[d] * __ldg(&a[d]);
    return s;
}

// write p (per src relation) and q (per dst relation) for node (type t, local n, factor k)
__device__ __forceinline__ void write_pq(int t, int n, int k, const float* vec, const float* at) {
    if (t == 0) {
        g_p[(c_ROFF[0] + n) * 2 + k] = dot25(vec, at + (0 * 2 + k) * 50);
        g_q[(c_COFF[1] + n) * 2 + k] = dot25(vec, at + (1 * 2 + k) * 50 + 25);
    } else if (t == 1) {
        #pragma unroll
        for (int e = 1; e < 8; e++)
            g_p[(c_ROFF[e] + n) * 2 + k] = dot25(vec, at + (e * 2 + k) * 50);
        g_q[(c_COFF[0] + n) * 2 + k] = dot25(vec, at + (0 * 2 + k) * 50 + 25);
    } else {
        g_q[(c_COFF[t] + n) * 2 + k] = dot25(vec, at + (t * 2 + k) * 50 + 25);
    }
}

// ---------------- initial projection + fused p/q ----------------------------------
__global__ void __launch_bounds__(128) k_init(Ptrs P) {
    __shared__ float Wsh[2][2][50 * 25];   // [which-type][k][d*25+f]
    int base_slot = blockIdx.x * 128;
    int node0 = base_slot >> 1;
    int nlast = (base_slot + 127) >> 1;
    if (nlast > TOTAL_NODES - 1) nlast = TOTAL_NODES - 1;
    int t0 = find_seg8(c_TOFF, node0);
    int t1 = find_seg8(c_TOFF, nlast);
    for (int i = threadIdx.x; i < 2 * 50 * 25; i += 128) {
        Wsh[0][0][i] = P.Wtk[(size_t)t0 * 2 * 50 * 25 + i];
        Wsh[1][0][i] = P.Wtk[(size_t)t1 * 2 * 50 * 25 + i];
    }
    __syncthreads();
    int slot = base_slot + threadIdx.x;
    if (slot >= TOTAL_NODES * 2) return;
    int node = slot >> 1, k = slot & 1;
    int t = find_seg8(c_TOFF, node);
    int sel = (t == t0) ? 0 : 1;
    const float* x = P.embin[t] + (size_t)(node - c_TOFF[t]) * 50;
    const float* w = &Wsh[sel][k][0];
    float out[25];
    #pragma unroll
    for (int f = 0; f < 25; f++) out[f] = 0.f;
    for (int d = 0; d < 50; d++) {
        float xd = __ldg(&x[d]);
        #pragma unroll
        for (int f = 0; f < 25; f++) out[f] += xd * w[d * 25 + f];
    }
    float nrm = 0.f;
    #pragma unroll
    for (int f = 0; f < 25; f++) {
        float s = out[f];
        s = (s >= 0.f) ? s : 0.2f * s;
        out[f] = s;
        nrm += s * s;
    }
    float inv = 1.f / fmaxf(sqrtf(nrm), 1e-12f);
    #pragma unroll
    for (int f = 0; f < 25; f++) out[f] *= inv;
    float* dst = g_emb + (size_t)node * NDIM + k * DKP;
    #pragma unroll
    for (int f = 0; f < 25; f++) dst[f] = out[f];
    dst[25] = 0.f; dst[26] = 0.f; dst[27] = 0.f;
    write_pq(t, node - c_TOFF[t], k, out, P.at);
}

// ---------------- zero scratch (own kernel: deterministic launch count) -----------
__global__ void k_zeroscratch() {
    int i = blockIdx.x * blockDim.x + threadIdx.x;
    if (i < TOTAL_ROWS * 2 + SCAN_NBLK) g_zero[i] = 0;
}

// ---------------- CSR build (edges constant across iterations) --------------------
__global__ void k_hist(Ptrs P) {
    int j = blockIdx.x * blockDim.x + threadIdx.x;
    if (j >= TOTAL_EDGES) return;
    int e = find_seg8(c_EOFF, j);
    int le = j - c_EOFF[e];
    int u = P.edge[e][le];
    atomicAdd(&g_zero[c_ROFF[e] + u], 1);   // rowcnt
}

// chained scan, 8 elems/thread, 33 blocks (all co-resident)
__global__ void __launch_bounds__(1024, 2) k_scan() {
    __shared__ int sh[1024];
    __shared__ int sh_prefix;
    int bid = blockIdx.x, tid = threadIdx.x;
    int base = bid * SCAN_ELEMS + tid * 8;
    int v[8];
    #pragma unroll
    for (int u = 0; u < 8; u++) {
        int i = base + u;
        v[u] = (i < TOTAL_ROWS) ? g_zero[i] : 0;
    }
    int tsum = 0;
    #pragma unroll
    for (int u = 0; u < 8; u++) tsum += v[u];
    sh[tid] = tsum;
    __syncthreads();
    #pragma unroll
    for (int off = 1; off < 1024; off <<= 1) {
        int t = (tid >= off) ? sh[tid - off] : 0;
        __syncthreads();
        sh[tid] += t;
        __syncthreads();
    }
    int excl = sh[tid] - tsum;
    int total = sh[1023];
    if (tid == 0) {
        int prefix = 0;
        if (bid > 0) {
            volatile int* flag = (volatile int*)&g_zero[2 * TOTAL_ROWS];
            while (flag[bid - 1] == 0) {}
            prefix = *((volatile int*)&g_blocksum[bid - 1]);
        }
        *((volatile int*)&g_blocksum[bid]) = prefix + total;
        __threadfence();
        *((volatile int*)&g_zero[2 * TOTAL_ROWS + bid]) = 1;
        sh_prefix = prefix;
    }
    __syncthreads();
    int p = sh_prefix + excl;
    #pragma unroll
    for (int u = 0; u < 8; u++) {
        int i = base + u;
        if (i < TOTAL_ROWS) g_rowptr[i] = p;
        p += v[u];
    }
    if (bid == SCAN_NBLK - 1 && tid == 1023) g_rowptr[TOTAL_ROWS] = sh_prefix + total;
}

__global__ void k_fill(Ptrs P) {
    int j = blockIdx.x * blockDim.x + threadIdx.x;
    if (j >= TOTAL_EDGES) return;
    int e = find_seg8(c_EOFF, j);
    int le = j - c_EOFF[e];
    int E = c_EOFF[e + 1] - c_EOFF[e];
    const int* ed = P.edge[e];
    int u = ed[le], c = ed[E + le];
    int row = c_ROFF[e] + u;
    int pos = g_rowptr[row] + atomicAdd(&g_zero[TOTAL_ROWS + row], 1);  // fill
    g_colidx[pos] = c;
}

// ---------------- fused: score+softmax+aggregate+transform (warp/row) -------------
// Part 1 (per warp): flash aggregation -> z lanes (float2, lane<28).
// Part 2: stage lrelu(z) in smem, compute z' = lrelu(z)@W, r = softmax_k(tanh(z').q)
// in the same kernel. W cached in smem. Eliminates the g_z round-trip.
__global__ void __launch_bounds__(256) k_rowtrans(Ptrs P) {
    __shared__ float Ws[625];
    __shared__ float zsh[8][56];     // per-warp staged lrelu(z)
    for (int i = threadIdx.x; i < 625; i += 256) Ws[i] = P.W[i];
    __syncthreads();

    int row  = (blockIdx.x * 256 + threadIdx.x) >> 5;
    int lane = threadIdx.x & 31;
    int w_id = (threadIdx.x >> 5);
    bool active = (row < TOTAL_ROWS);
    int e = 0, base = 0, deg = 0, coff = 0, nbase = 0;
    float2 pv = make_float2(0.f, 0.f);
    if (active) {
        e = find_seg8(c_ROFF, row);
        base = g_rowptr[row];
        deg  = g_rowptr[row + 1] - base;
        coff  = c_COFF[e];
        nbase = c_TOFF[c_DST[e]];
        pv = ((const float2*)g_p)[row];
    }
    int dlane = (lane < 28) ? lane : 27;   // lanes 28-31 duplicate lane 27

    float s = 0.f;
    float2 accA = make_float2(0.f, 0.f), accB = make_float2(0.f, 0.f);

    for (int i0 = 0; i0 < deg; i0 += 32) {
        int i = i0 + lane;
        int c = 0; float w = 0.f;
        if (i < deg) {
            c = __ldg(&g_colidx[base + i]);
            float2 qv = __ldg(&((const float2*)g_q)[coff + c]);
            float v = 0.5f * (fmaxf(pv.x + qv.x, 0.f) + fmaxf(pv.y + qv.y, 0.f));
            w = __expf(v);
            s += w;
        }
        int nn = deg - i0; if (nn > 32) nn = 32;
        int nn8 = (nn + 7) & ~7;           // inactive lanes have w=0, c=0 -> harmless
        for (int jj = 0; jj < nn8; jj += 8) {
            float aw[8]; int cc[8];
            #pragma unroll
            for (int u = 0; u < 8; u++) {
                aw[u] = __shfl_sync(0xffffffffu, w, jj + u);
                cc[u] = __shfl_sync(0xffffffffu, c, jj + u);
            }
            float2 f[8];
            #pragma unroll
            for (int u = 0; u < 8; u++)
                f[u] = __ldg(&((const float2*)(g_emb + (size_t)(nbase + cc[u]) * NDIM))[dlane]);
            #pragma unroll
            for (int u = 0; u < 8; u += 2) {
                accA.x += aw[u] * f[u].x;     accA.y += aw[u] * f[u].y;
                accB.x += aw[u+1] * f[u+1].x; accB.y += aw[u+1] * f[u+1].y;
            }
        }
    }
    #pragma unroll
    for (int off = 16; off; off >>= 1)
        s += __shfl_xor_sync(0xffffffffu, s, off);
    float invS = (deg > 0) ? (1.f / s) : 0.f;

    // stage lrelu(z) into shared (apply leaky relu at write time)
    if (lane < 28) {
        float zx = (accA.x + accB.x) * invS;
        float zy = (accA.y + accB.y) * invS;
        zsh[w_id][2 * lane]     = (zx >= 0.f) ? zx : 0.2f * zx;
        zsh[w_id][2 * lane + 1] = (zy >= 0.f) ? zy : 0.2f * zy;
    }
    __syncwarp();

    // transform: lane f<25 computes out[k][f] = sum_d zsh[k*28+d]*W[d][f]
    float out0 = 0.f, out1 = 0.f;
    if (lane < 25) {
        const float* z0 = &zsh[w_id][0];
        const float* z1 = &zsh[w_id][28];
        #pragma unroll
        for (int d = 0; d < 25; d++) {
            float wdf = Ws[d * 25 + lane];
            out0 += z0[d] * wdf;
            out1 += z1[d] * wdf;
        }
    }
    float qrf = (active && lane < 25) ? __ldg(&P.q_rela[e * 25 + lane]) : 0.f;
    float p0 = fast_tanh(out0) * qrf;
    float p1 = fast_tanh(out1) * qrf;
    if (lane >= 25) { p0 = 0.f; p1 = 0.f; }
    #pragma unroll
    for (int off = 16; off; off >>= 1) {
        p0 += __shfl_xor_sync(0xffffffffu, p0, off);
        p1 += __shfl_xor_sync(0xffffffffu, p1, off);
    }
    if (active) {
        if (lane == 0) {
            float mm = fmaxf(p0, p1);
            float e0 = __expf(p0 - mm), e1 = __expf(p1 - mm);
            float inv = 1.f / (e0 + e1);
            ((float2*)g_r)[row] = make_float2(e0 * inv, e1 * inv);
        }
        float* zr = g_z + (size_t)row * NDIM;
        if (lane < 25) {
            zr[lane] = out0;
            zr[DKP + lane] = out1;
        }
    }
}

// ---------------- ego aggregation + l2 normalize + fused p/q refresh --------------
__global__ void __launch_bounds__(256) k_agg(Ptrs P) {
    int slot = blockIdx.x * 256 + threadIdx.x;
    if (slot >= OUT_ROWS * 2) return;
    int node = slot >> 1, k = slot & 1;
    float acc[25];
    float* er = g_emb + (size_t)node * NDIM + k * DKP;
    #pragma unroll
    for (int d = 0; d < 25; d++) acc[d] = er[d];
    if (node < 60000) {                 // type 0: relation 0 only
        float r = g_r[node * 2 + k];
        const float* zz = g_z + (size_t)node * NDIM + k * DKP;
        #pragma unroll
        for (int d = 0; d < 25; d++) acc[d] += r * zz[d];
    } else {                            // type 1: relations 1..7
        int n = node - 60000;
        #pragma unroll
        for (int e = 1; e < 8; e++) {
            int row = c_ROFF[e] + n;
            float r = g_r[row * 2 + k];
            const float* zz = g_z + (size_t)row * NDIM + k * DKP;
            #pragma unroll
            for (int d = 0; d < 25; d++) acc[d] += r * zz[d];
        }
    }
    float nrm = 0.f;
    #pragma unroll
    for (int d = 0; d < 25; d++) nrm += acc[d] * acc[d];
    float inv = 1.f / fmaxf(sqrtf(nrm), 1e-12f);
    #pragma unroll
    for (int d = 0; d < 25; d++) acc[d] *= inv;
    #pragma unroll
    for (int d = 0; d < 25; d++) er[d] = acc[d];
    int t = (node < 60000) ? 0 : 1;
    write_pq(t, (t == 0) ? node : node - 60000, k, acc, P.at);
}

// ---------------- output: [n, k*25+d] for user then item --------------------------
__global__ void k_out(float* __restrict__ out) {
    int idx = blockIdx.x * blockDim.x + threadIdx.x;
    if (idx >= OUT_ROWS * 50) return;
    int r = idx / 50, c = idx - r * 50;
    int k = c / 25, d = c - k * 25;
    out[idx] = g_emb[(size_t)r * NDIM + k * DKP + d];
}

} // anonymous namespace

extern "C" void kernel_launch(void* const* d_in, const int* in_sizes, int n_in,
                              void* d_out, int out_size) {
    Ptrs P;
    for (int i = 0; i < 8; i++) P.edge[i]  = (const int*)d_in[i];
    for (int i = 0; i < 8; i++) P.embin[i] = (const float*)d_in[8 + i];
    P.Wtk    = (const float*)d_in[16];
    P.at     = (const float*)d_in[17];
    P.W      = (const float*)d_in[18];
    P.q_rela = (const float*)d_in[19];

    // launch indices 0..4 fixed, so k_rowtrans (first iter) is launch #5
    k_init<<<(TOTAL_NODES * 2 + 127) / 128, 128>>>(P);                      // 0
    k_zeroscratch<<<(TOTAL_ROWS * 2 + SCAN_NBLK + 255) / 256, 256>>>();     // 1
    k_hist<<<(TOTAL_EDGES + 255) / 256, 256>>>(P);                          // 2
    k_scan<<<SCAN_NBLK, 1024>>>();                                          // 3
    k_fill<<<(TOTAL_EDGES + 255) / 256, 256>>>(P);                          // 4

    for (int it = 0; it < 4; it++) {
        k_rowtrans<<<(TOTAL_ROWS * 32 + 255) / 256, 256>>>(P);              // 5 on it=0
        k_agg<<<(OUT_ROWS * 2 + 255) / 256, 256>>>(P);
    }
    k_out<<<(OUT_ROWS * 50 + 255) / 256, 256>>>((float*)d_out);
}

// round 5
// speedup vs baseline: 1.2869x; 1.0055x over previous
#include <cuda_runtime.h>
#include <cuda_fp16.h>
#include <math.h>

namespace {

constexpr int DKP = 28;              // padded factor dim (25 -> 28)
constexpr int NDIM = 2 * DKP;        // 56 floats per node (fp32 master)
constexpr int HS   = 28;             // half2 stride per node in fp16 mirror
constexpr int TOTAL_NODES = 180000;  // 60000 + 30000 + 6*15000
constexpr int TOTAL_ROWS  = 270000;  // 60000 + 7*30000
constexpr int TOTAL_COLS  = 180000;  // 30000 + 60000 + 6*15000
constexpr int TOTAL_EDGES = 3800000; // 2*1e6 + 6*3e5
constexpr int OUT_ROWS = 90000;
constexpr int SCAN_ELEMS = 8192;     // per block (1024 thr x 8)
constexpr int SCAN_NBLK = (TOTAL_ROWS + SCAN_ELEMS - 1) / SCAN_ELEMS; // 33

__constant__ int c_EOFF[9] = {0,1000000,2000000,2300000,2600000,2900000,3200000,3500000,3800000};
__constant__ int c_ROFF[9] = {0,60000,90000,120000,150000,180000,210000,240000,270000};
__constant__ int c_COFF[9] = {0,30000,90000,105000,120000,135000,150000,165000,180000};
__constant__ int c_TOFF[9] = {0,60000,90000,105000,120000,135000,150000,165000,180000};
__constant__ int c_SRC[8]  = {0,1,1,1,1,1,1,1};
__constant__ int c_DST[8]  = {1,0,2,3,4,5,6,7};

__device__ float    g_emb [(size_t)TOTAL_NODES * NDIM + 16]; // fp32 master
__device__ unsigned g_embh[(size_t)TOTAL_NODES * HS];        // fp16 mirror: half2(k0[d],k1[d])
__device__ float    g_z   [(size_t)TOTAL_ROWS  * NDIM];      // transformed messages z'
__device__ float    g_p   [TOTAL_ROWS * 2];
__device__ __half   g_qh  [TOTAL_COLS * 2];                  // fp16 q, pair-packed
__device__ float    g_r   [TOTAL_ROWS * 2];
__device__ int      g_rowcnt[TOTAL_ROWS];
__device__ int      g_rowptr[TOTAL_ROWS + 1];
__device__ int      g_blocksum[SCAN_NBLK];
__device__ int      g_rank  [TOTAL_EDGES];
__device__ int      g_colidx[TOTAL_EDGES];

struct Ptrs {
    const int*   edge[8];
    const float* embin[8];
    const float* Wtk;
    const float* at;
    const float* W;
    const float* q_rela;
};

__device__ __forceinline__ int find_seg8(const int* off, int x) {
    int e = 0;
    #pragma unroll
    for (int i = 1; i < 8; i++) e += (x >= off[i]);
    return e;
}

__device__ __forceinline__ float fast_tanh(float x) {
    float y;
    asm("tanh.approx.f32 %0, %1;" : "=f"(y) : "f"(x));
    return y;
}

__device__ __forceinline__ float dot25(const float* v, const float* a) {
    float s = 0.f;
    #pragma unroll
    for (int d = 0; d < 25; d++) s += v[d] * __ldg(&a[d]);
    return s;
}

// write p (fp32) and q (fp16) for node (type t, local n, factor k)
__device__ __forceinline__ void write_pq(int t, int n, int k, const float* vec, const float* at) {
    if (t == 0) {
        g_p [(c_ROFF[0] + n) * 2 + k] = dot25(vec, at + (0 * 2 + k) * 50);
        g_qh[(c_COFF[1] + n) * 2 + k] = __float2half(dot25(vec, at + (1 * 2 + k) * 50 + 25));
    } else if (t == 1) {
        #pragma unroll
        for (int e = 1; e < 8; e++)
            g_p[(c_ROFF[e] + n) * 2 + k] = dot25(vec, at + (e * 2 + k) * 50);
        g_qh[(c_COFF[0] + n) * 2 + k] = __float2half(dot25(vec, at + (0 * 2 + k) * 50 + 25));
    } else {
        g_qh[(c_COFF[t] + n) * 2 + k] = __float2half(dot25(vec, at + (t * 2 + k) * 50 + 25));
    }
}

// fp16 mirror write: factor-k halves at node*56 + 2d + k  (== half2 lane d)
__device__ __forceinline__ void write_mirror(int node, int k, const float* vec) {
    __half* h = (__half*)g_embh;
    #pragma unroll
    for (int d = 0; d < 25; d++) h[(size_t)node * 2 * HS + 2 * d + k] = __float2half(vec[d]);
}

// ---------------- initial projection + fused p/q + mirror -------------------------
__global__ void __launch_bounds__(128) k_init(Ptrs P) {
    __shared__ float Wsh[2][2][50 * 25];   // [which-type][k][d*25+f]
    int base_slot = blockIdx.x * 128;
    int node0 = base_slot >> 1;
    int nlast = (base_slot + 127) >> 1;
    if (nlast > TOTAL_NODES - 1) nlast = TOTAL_NODES - 1;
    int t0 = find_seg8(c_TOFF, node0);
    int t1 = find_seg8(c_TOFF, nlast);
    for (int i = threadIdx.x; i < 2 * 50 * 25; i += 128) {
        Wsh[0][0][i] = P.Wtk[(size_t)t0 * 2 * 50 * 25 + i];
        Wsh[1][0][i] = P.Wtk[(size_t)t1 * 2 * 50 * 25 + i];
    }
    __syncthreads();
    int slot = base_slot + threadIdx.x;
    if (slot >= TOTAL_NODES * 2) return;
    int node = slot >> 1, k = slot & 1;
    int t = find_seg8(c_TOFF, node);
    int sel = (t == t0) ? 0 : 1;
    const float* x = P.embin[t] + (size_t)(node - c_TOFF[t]) * 50;
    const float* w = &Wsh[sel][k][0];
    float out[25];
    #pragma unroll
    for (int f = 0; f < 25; f++) out[f] = 0.f;
    for (int d = 0; d < 50; d++) {
        float xd = __ldg(&x[d]);
        #pragma unroll
        for (int f = 0; f < 25; f++) out[f] += xd * w[d * 25 + f];
    }
    float nrm = 0.f;
    #pragma unroll
    for (int f = 0; f < 25; f++) {
        float s = out[f];
        s = (s >= 0.f) ? s : 0.2f * s;
        out[f] = s;
        nrm += s * s;
    }
    float inv = 1.f / fmaxf(sqrtf(nrm), 1e-12f);
    #pragma unroll
    for (int f = 0; f < 25; f++) out[f] *= inv;
    float* dst = g_emb + (size_t)node * NDIM + k * DKP;
    #pragma unroll
    for (int f = 0; f < 25; f++) dst[f] = out[f];
    dst[25] = 0.f; dst[26] = 0.f; dst[27] = 0.f;
    write_mirror(node, k, out);
    write_pq(t, node - c_TOFF[t], k, out, P.at);
}

// ---------------- zero rowcnt -----------------------------------------------------
__global__ void k_zeroscratch() {
    int i = blockIdx.x * blockDim.x + threadIdx.x;
    if (i < TOTAL_ROWS) g_rowcnt[i] = 0;
}

// ---------------- CSR build: hist also records each edge's within-row rank --------
__global__ void k_hist(Ptrs P) {
    int j = blockIdx.x * blockDim.x + threadIdx.x;
    if (j >= TOTAL_EDGES) return;
    int e = find_seg8(c_EOFF, j);
    int le = j - c_EOFF[e];
    int u = P.edge[e][le];
    g_rank[j] = atomicAdd(&g_rowcnt[c_ROFF[e] + u], 1);
}

// 3-kernel scan, 8 elems/thread
__global__ void __launch_bounds__(1024) k_scanA() {
    __shared__ int sh[1024];
    int bid = blockIdx.x, tid = threadIdx.x;
    int base = bid * SCAN_ELEMS + tid * 8;
    int v[8];
    #pragma unroll
    for (int u = 0; u < 8; u++) {
        int i = base + u;
        v[u] = (i < TOTAL_ROWS) ? g_rowcnt[i] : 0;
    }
    int tsum = 0;
    #pragma unroll
    for (int u = 0; u < 8; u++) tsum += v[u];
    sh[tid] = tsum;
    __syncthreads();
    #pragma unroll
    for (int off = 1; off < 1024; off <<= 1) {
        int t = (tid >= off) ? sh[tid - off] : 0;
        __syncthreads();
        sh[tid] += t;
        __syncthreads();
    }
    int p = sh[tid] - tsum;   // local exclusive
    #pragma unroll
    for (int u = 0; u < 8; u++) {
        int i = base + u;
        if (i < TOTAL_ROWS) g_rowptr[i] = p;
        p += v[u];
    }
    if (tid == 1023) g_blocksum[bid] = sh[1023];
}

__global__ void k_scanB() {
    // single warp scans 33 block sums (exclusive)
    int tid = threadIdx.x;
    int v = (tid < SCAN_NBLK) ? g_blocksum[tid] : 0;
    int s = v;
    #pragma unroll
    for (int off = 1; off < 64; off <<= 1) {
        int t = __shfl_up_sync(0xffffffffu, s, off);
        if ((tid & 31) >= off) s += t;
    }
    // 64 threads: second warp needs first warp's total
    __shared__ int w0tot;
    if (tid == 31) w0tot = s;
    __syncthreads();
    if (tid >= 32) s += w0tot;
    if (tid < SCAN_NBLK) g_blocksum[tid] = s - v;
}

__global__ void k_scanC() {
    int i = blockIdx.x * blockDim.x + threadIdx.x;
    if (i < TOTAL_ROWS) g_rowptr[i] += g_blocksum[i >> 13];
    if (i == 0) g_rowptr[TOTAL_ROWS] = TOTAL_EDGES;
}

__global__ void k_fill(Ptrs P) {
    int j = blockIdx.x * blockDim.x + threadIdx.x;
    if (j >= TOTAL_EDGES) return;
    int e = find_seg8(c_EOFF, j);
    int le = j - c_EOFF[e];
    int E = c_EOFF[e + 1] - c_EOFF[e];
    const int* ed = P.edge[e];
    int u = ed[le], c = ed[E + le];
    int row = c_ROFF[e] + u;
    g_colidx[g_rowptr[row] + g_rank[j]] = c;
}

// ---------------- fused: score+softmax+aggregate+transform (warp/row) -------------
// fp16 gather: lane d<25 loads half2(k0[d],k1[d]) -> 4 sectors/edge vs 7 fp32.
__global__ void __launch_bounds__(256) k_rowtrans(Ptrs P) {
    __shared__ float Ws[625];
    __shared__ float zsh[8][56];     // per-warp staged lrelu(z): [0..24]=k0, [28..52]=k1
    for (int i = threadIdx.x; i < 625; i += 256) Ws[i] = P.W[i];
    __syncthreads();

    int row  = (blockIdx.x * 256 + threadIdx.x) >> 5;
    int lane = threadIdx.x & 31;
    int w_id = (threadIdx.x >> 5);
    bool active = (row < TOTAL_ROWS);
    int e = 0, base = 0, deg = 0, coff = 0, nbase = 0;
    float2 pv = make_float2(0.f, 0.f);
    if (active) {
        e = find_seg8(c_ROFF, row);
        base = g_rowptr[row];
        deg  = g_rowptr[row + 1] - base;
        coff  = c_COFF[e];
        nbase = c_TOFF[c_DST[e]];
        pv = ((const float2*)g_p)[row];
    }
    int dlane = (lane < 25) ? lane : 24;   // lanes 25-31 duplicate lane 24 (discarded)

    float s = 0.f;
    float accA = 0.f, accB = 0.f;          // lane d: factor0[d], factor1[d]

    const unsigned* qh32 = (const unsigned*)g_qh;
    for (int i0 = 0; i0 < deg; i0 += 32) {
        int i = i0 + lane;
        int c = 0; float w = 0.f;
        if (i < deg) {
            c = __ldg(&g_colidx[base + i]);
            unsigned qraw = __ldg(&qh32[coff + c]);
            float2 qv = __half22float2(*(const __half2*)&qraw);
            float v = 0.5f * (fmaxf(pv.x + qv.x, 0.f) + fmaxf(pv.y + qv.y, 0.f));
            w = __expf(v);
            s += w;
        }
        int nn = deg - i0; if (nn > 32) nn = 32;
        int nn8 = (nn + 7) & ~7;           // inactive lanes: w=0, c=0 -> harmless
        for (int jj = 0; jj < nn8; jj += 8) {
            float aw[8]; int cc[8];
            #pragma unroll
            for (int u = 0; u < 8; u++) {
                aw[u] = __shfl_sync(0xffffffffu, w, jj + u);
                cc[u] = __shfl_sync(0xffffffffu, c, jj + u);
            }
            unsigned hv[8];
            #pragma unroll
            for (int u = 0; u < 8; u++)
                hv[u] = __ldg(&g_embh[(size_t)(nbase + cc[u]) * HS + dlane]);
            #pragma unroll
            for (int u = 0; u < 8; u++) {
                float2 f = __half22float2(*(const __half2*)&hv[u]);
                accA += aw[u] * f.x;
                accB += aw[u] * f.y;
            }
        }
    }
    #pragma unroll
    for (int off = 16; off; off >>= 1)
        s += __shfl_xor_sync(0xffffffffu, s, off);
    float invS = (deg > 0) ? (1.f / s) : 0.f;

    if (lane < 25) {
        float zx = accA * invS;
        float zy = accB * invS;
        zsh[w_id][lane]      = (zx >= 0.f) ? zx : 0.2f * zx;
        zsh[w_id][28 + lane] = (zy >= 0.f) ? zy : 0.2f * zy;
    }
    __syncwarp();

    // transform: lane f<25 computes out[k][f] = sum_d zsh[k][d]*W[d][f]
    float out0 = 0.f, out1 = 0.f;
    if (lane < 25) {
        const float* z0 = &zsh[w_id][0];
        const float* z1 = &zsh[w_id][28];
        #pragma unroll
        for (int d = 0; d < 25; d++) {
            float wdf = Ws[d * 25 + lane];
            out0 += z0[d] * wdf;
            out1 += z1[d] * wdf;
        }
    }
    float qrf = (active && lane < 25) ? __ldg(&P.q_rela[e * 25 + lane]) : 0.f;
    float p0 = fast_tanh(out0) * qrf;
    float p1 = fast_tanh(out1) * qrf;
    if (lane >= 25) { p0 = 0.f; p1 = 0.f; }
    #pragma unroll
    for (int off = 16; off; off >>= 1) {
        p0 += __shfl_xor_sync(0xffffffffu, p0, off);
        p1 += __shfl_xor_sync(0xffffffffu, p1, off);
    }
    if (active) {
        if (lane == 0) {
            float mm = fmaxf(p0, p1);
            float e0 = __expf(p0 - mm), e1 = __expf(p1 - mm);
            float inv = 1.f / (e0 + e1);
            ((float2*)g_r)[row] = make_float2(e0 * inv, e1 * inv);
        }
        float* zr = g_z + (size_t)row * NDIM;
        if (lane < 25) {
            zr[lane] = out0;
            zr[DKP + lane] = out1;
        }
    }
}

// ---------------- ego aggregation + l2 normalize + p/q + mirror refresh -----------
__global__ void __launch_bounds__(256) k_agg(Ptrs P) {
    int slot = blockIdx.x * 256 + threadIdx.x;
    if (slot >= OUT_ROWS * 2) return;
    int node = slot >> 1, k = slot & 1;
    float acc[25];
    float* er = g_emb + (size_t)node * NDIM + k * DKP;
    #pragma unroll
    for (int d = 0; d < 25; d++) acc[d] = er[d];
    if (node < 60000) {                 // type 0: relation 0 only
        float r = g_r[node * 2 + k];
        const float* zz = g_z + (size_t)node * NDIM + k * DKP;
        #pragma unroll
        for (int d = 0; d < 25; d++) acc[d] += r * zz[d];
    } else {                            // type 1: relations 1..7
        int n = node - 60000;
        #pragma unroll
        for (int e = 1; e < 8; e++) {
            int row = c_ROFF[e] + n;
            float r = g_r[row * 2 + k];
            const float* zz = g_z + (size_t)row * NDIM + k * DKP;
            #pragma unroll
            for (int d = 0; d < 25; d++) acc[d] += r * zz[d];
        }
    }
    float nrm = 0.f;
    #pragma unroll
    for (int d = 0; d < 25; d++) nrm += acc[d] * acc[d];
    float inv = 1.f / fmaxf(sqrtf(nrm), 1e-12f);
    #pragma unroll
    for (int d = 0; d < 25; d++) acc[d] *= inv;
    #pragma unroll
    for (int d = 0; d < 25; d++) er[d] = acc[d];
    write_mirror(node, k, acc);
    int t = (node < 60000) ? 0 : 1;
    write_pq(t, (t == 0) ? node : node - 60000, k, acc, P.at);
}

// ---------------- output: [n, k*25+d] for user then item --------------------------
__global__ void k_out(float* __restrict__ out) {
    int idx = blockIdx.x * blockDim.x + threadIdx.x;
    if (idx >= OUT_ROWS * 50) return;
    int r = idx / 50, c = idx - r * 50;
    int k = c / 25, d = c - k * 25;
    out[idx] = g_emb[(size_t)r * NDIM + k * DKP + d];
}

} // anonymous namespace

extern "C" void kernel_launch(void* const* d_in, const int* in_sizes, int n_in,
                              void* d_out, int out_size) {
    Ptrs P;
    for (int i = 0; i < 8; i++) P.edge[i]  = (const int*)d_in[i];
    for (int i = 0; i < 8; i++) P.embin[i] = (const float*)d_in[8 + i];
    P.Wtk    = (const float*)d_in[16];
    P.at     = (const float*)d_in[17];
    P.W      = (const float*)d_in[18];
    P.q_rela = (const float*)d_in[19];

    k_init<<<(TOTAL_NODES * 2 + 127) / 128, 128>>>(P);
    k_zeroscratch<<<(TOTAL_ROWS + 255) / 256, 256>>>();
    k_hist<<<(TOTAL_EDGES + 255) / 256, 256>>>(P);
    k_scanA<<<SCAN_NBLK, 1024>>>();
    k_scanB<<<1, 64>>>();
    k_scanC<<<(TOTAL_ROWS + 255) / 256, 256>>>();
    k_fill<<<(TOTAL_EDGES + 255) / 256, 256>>>(P);

    for (int it = 0; it < 4; it++) {
        k_rowtrans<<<(TOTAL_ROWS * 32 + 255) / 256, 256>>>(P);
        k_agg<<<(OUT_ROWS * 2 + 255) / 256, 256>>>(P);
    }
    k_out<<<(OUT_ROWS * 50 + 255) / 256, 256>>>((float*)d_out);
}